// round 16
// baseline (speedup 1.0000x reference)
#include <cuda_runtime.h>
#include <cuda_fp16.h>
#include <math.h>
#include <stdint.h>

// ---------------- packed f32x2 helpers (final conv) ----------------
__device__ __forceinline__ unsigned long long pk2(float x, float y) {
    unsigned long long r;
    asm("mov.b64 %0, {%1, %2};" : "=l"(r) : "f"(x), "f"(y));
    return r;
}
__device__ __forceinline__ void fma2(unsigned long long& d,
                                     unsigned long long a, unsigned long long b) {
    asm("fma.rn.f32x2 %0, %1, %2, %0;" : "+l"(d) : "l"(a), "l"(b));
}
union F4 { float4 v; float f[4]; unsigned long long u[2]; };

// ---------------- mma.sync helpers ----------------
__device__ __forceinline__ void ldm4(uint32_t* r, uint32_t addr) {
    asm volatile("ldmatrix.sync.aligned.m8n8.x4.shared.b16 {%0,%1,%2,%3}, [%4];"
                 : "=r"(r[0]), "=r"(r[1]), "=r"(r[2]), "=r"(r[3]) : "r"(addr));
}
__device__ __forceinline__ void mma16816(float& d0, float& d1, float& d2, float& d3,
                                         const uint32_t* a, uint32_t b0, uint32_t b1) {
    asm volatile(
        "mma.sync.aligned.m16n8k16.row.col.f32.f16.f16.f32 "
        "{%0,%1,%2,%3}, {%4,%5,%6,%7}, {%8,%9}, {%0,%1,%2,%3};"
        : "+f"(d0), "+f"(d1), "+f"(d2), "+f"(d3)
        : "r"(a[0]), "r"(a[1]), "r"(a[2]), "r"(a[3]), "r"(b0), "r"(b1));
}
__device__ __forceinline__ uint32_t smem_u32(const void* p) {
    uint32_t a;
    asm("{ .reg .u64 t; cvta.to.shared.u64 t, %1; cvt.u32.u64 %0, t; }"
        : "=r"(a) : "l"(p));
    return a;
}
__device__ __forceinline__ uint32_t packh(float a, float b) {
    __half2 h = __halves2half2(__float2half_rn(a), __float2half_rn(b));
    return *(uint32_t*)&h;
}

// single extern smem symbol shared by kernels
extern __shared__ float smext[];

// ---------------- scratch ----------------
#define NPIX 16384
__device__ __align__(16) float  g_bufA[4 * 256 * NPIX];
__device__ __align__(16) float  g_bufB[4 * 256 * NPIX];
__device__ __align__(16) __half g_bufC[4 * 256 * NPIX];   // NHWC fp16
__device__ __align__(16) float  g_off [4 * 100 * NPIX];
__device__ __align__(16) uint2  g_bh  [50 * 8 * 32 * 32];
__device__ __align__(16) uint2  g_obh [50 * 8 * 16 * 32];
__device__ __align__(16) float  g_rT  [256 * 128];
__device__ float g_pool[1024];
__device__ float g_scale[1024];

// ---------------- concat -> NHWC fp16 C ----------
__global__ void __launch_bounds__(256) concat_nhwc(
    const float* __restrict__ bev1, const float* __restrict__ bev2,
    __half* __restrict__ C) {
    __shared__ float tile[32][33];
    const int bp = blockIdx.x, bc = blockIdx.y, b = blockIdx.z;
    const int tx = threadIdx.x & 31, ty = threadIdx.x >> 5;
    const float* src = ((bc < 4)
        ? bev1 + ((size_t)b * 128 + bc * 32) * NPIX
        : bev2 + ((size_t)b * 128 + (bc - 4) * 32) * NPIX) + bp * 32;
#pragma unroll
    for (int r = 0; r < 4; r++) {
        int c = ty + r * 8;
        tile[c][tx] = src[(size_t)c * NPIX + tx];
    }
    __syncthreads();
    __half* dst = C + ((size_t)b * NPIX + bp * 32) * 256 + bc * 32;
#pragma unroll
    for (int r = 0; r < 4; r++) {
        int p = ty + r * 8;
        dst[(size_t)p * 256 + tx] = __float2half_rn(tile[tx][p]);
    }
}

// ---------------- NCHW -> NHWC fp16 transpose with fused SE scale ----------
__global__ void __launch_bounds__(256) to_nhwc_scaled(
    const float* __restrict__ in, const float* __restrict__ sc,
    __half* __restrict__ outp) {
    __shared__ float tile[32][33];
    __shared__ float sSc[32];
    const int bp = blockIdx.x, bc = blockIdx.y, b = blockIdx.z;
    const int tx = threadIdx.x & 31, ty = threadIdx.x >> 5;
    if (threadIdx.x < 32) sSc[threadIdx.x] = sc[b * 256 + bc * 32 + threadIdx.x];
    const float* src = in + ((size_t)b * 256 + bc * 32) * NPIX + bp * 32;
#pragma unroll
    for (int r = 0; r < 4; r++) {
        int c = ty + r * 8;
        tile[c][tx] = src[(size_t)c * NPIX + tx];
    }
    __syncthreads();
    __half* dst = outp + ((size_t)b * NPIX + bp * 32) * 256 + bc * 32;
    const float s = sSc[tx];
#pragma unroll
    for (int r = 0; r < 4; r++) {
        int p = ty + r * 8;
        dst[(size_t)p * 256 + tx] = __float2half_rn(tile[tx][p] * s);
    }
}

// ---------------- weight prep: dcn hi + off hi fragment packs --------------
__global__ void prep_weights(const float* __restrict__ dcnw,
                             const float* __restrict__ offw,
                             uint2* __restrict__ BH,
                             uint2* __restrict__ OBH) {
    int idx = blockIdx.x * 256 + threadIdx.x;
    if (idx < 409600) {
        const int t  = idx & 31;
        const int j  = (idx >> 5) & 31;
        const int s  = (idx >> 10) & 7;
        const int gk = idx >> 13;
        const int k = gk % 25, g = gk / 25;
        const int o = j * 8 + (t >> 2);
        const int c0 = s * 16 + 2 * (t & 3);
        float w0 = dcnw[o * 6400 + (g * 128 + c0    ) * 25 + k] * 64.f;
        float w1 = dcnw[o * 6400 + (g * 128 + c0 + 1) * 25 + k] * 64.f;
        float w8 = dcnw[o * 6400 + (g * 128 + c0 + 8) * 25 + k] * 64.f;
        float w9 = dcnw[o * 6400 + (g * 128 + c0 + 9) * 25 + k] * 64.f;
        BH[idx] = make_uint2(packh(__half2float(__float2half_rn(w0)),
                                   __half2float(__float2half_rn(w1))),
                             packh(__half2float(__float2half_rn(w8)),
                                   __half2float(__float2half_rn(w9))));
    } else if (idx < 614400) {
        const int i2 = idx - 409600;
        const int t  = i2 & 31;
        const int j  = (i2 >> 5) & 15;
        const int s  = (i2 >> 9) & 7;
        const int it = i2 >> 12;
        const int k = it >> 1, h = it & 1;
        const int o = j * 8 + (t >> 2);
        const int c0 = h * 128 + s * 16 + 2 * (t & 3);
        float w0 = 0.f, w1 = 0.f, w8 = 0.f, w9 = 0.f;
        if (o < 100) {
            w0 = offw[o * 6400 + (c0    ) * 25 + k] * 1024.f;
            w1 = offw[o * 6400 + (c0 + 1) * 25 + k] * 1024.f;
            w8 = offw[o * 6400 + (c0 + 8) * 25 + k] * 1024.f;
            w9 = offw[o * 6400 + (c0 + 9) * 25 + k] * 1024.f;
        }
        OBH[i2] = make_uint2(packh(__half2float(__float2half_rn(w0)),
                                   __half2float(__float2half_rn(w1))),
                             packh(__half2float(__float2half_rn(w8)),
                                   __half2float(__float2half_rn(w9))));
    }
}

__global__ void transpose_redw(const float* __restrict__ w, float* __restrict__ dst) {
    int idx = blockIdx.x * 256 + threadIdx.x;
    int o = idx & 127;
    int c = idx >> 7;
    dst[idx] = w[o * 256 + c];
}

// ---------------- offset conv via mma.sync (fp16 in, single product) -------
// dynamic smem: uint32 Sbuf[2][4352] = 34,816 B; 3 CTAs/SM
__global__ void __launch_bounds__(256, 3) offconv_hmma(
    const __half* __restrict__ xh,   // NHWC fp16 [b][p][256]
    const uint2* __restrict__ OBH,
    const float* __restrict__ offb,
    float* __restrict__ offout) {
    uint32_t* Sbuf = (uint32_t*)smext;

    const int tid = threadIdx.x;
    const int lane = tid & 31, warp = tid >> 5;
    const int b = blockIdx.y;
    const int row = blockIdx.x >> 1;
    const int px0 = (blockIdx.x & 1) << 6;

    const int wo = warp & 1;
    const int wp = warp >> 1;
    const int sh = warp & 1;
    const int cq = warp >> 1;
    const int lg = lane >> 3;
    const int c0s = cq * 32 + (lane & 7) * 4;

    float d[32];
#pragma unroll
    for (int q = 0; q < 32; q++) d[q] = 0.f;

    const uint32_t sbase = smem_u32(Sbuf);
    const uint32_t lanePat = (lane & 15) * 272 + (lane >> 4) * 16;
    const __half* xb = xh + (size_t)b * NPIX * 256;

    auto sample_tap = [&](int it2, uint32_t* ShB) {
        const int k2 = it2 >> 1, h2 = it2 & 1;
        const int kh2 = k2 / 5, kw2 = k2 % 5;
        const int gy2 = row + kh2 - 2;
        const bool vy2 = (gy2 >= 0) & (gy2 < 128);
#pragma unroll
        for (int j = 0; j < 8; j++) {
            const int p = sh * 32 + j * 4 + lg;
            const int gx = px0 + p + kw2 - 2;
            uint2 va = make_uint2(0u, 0u);
            if (vy2 && gx >= 0 && gx < 128)
                va = *(const uint2*)(xb + ((size_t)gy2 * 128 + gx) * 256 + h2 * 128 + c0s);
            *(uint2*)&ShB[p * 68 + (c0s >> 1)] = va;
        }
    };

    sample_tap(0, Sbuf);
    __syncthreads();

    for (int it = 0; it < 50; it++) {
        const int cur = it & 1;
        if (it < 49) sample_tap(it + 1, Sbuf + (cur ^ 1) * 4352);
        const uint32_t aH = sbase + cur * 17408 + lanePat;
        const uint2* BHt = OBH + ((size_t)it * 8 * 16 + wo * 8) * 32 + lane;
#pragma unroll
        for (int s = 0; s < 8; s++) {
            uint32_t Ah[4];
            ldm4(Ah, aH + (wp * 16) * 272 + s * 32);
            const uint2* bh = BHt + (size_t)s * 512;
#pragma unroll
            for (int j2 = 0; j2 < 8; j2++) {
                uint2 Bh = bh[j2 * 32];
                float* dd = &d[j2 * 4];
                mma16816(dd[0], dd[1], dd[2], dd[3], Ah, Bh.x, Bh.y);
            }
        }
        __syncthreads();
    }

    const int g2 = lane >> 2, tig = lane & 3;
    const int pxl = wp * 16 + g2;
    const size_t outbase = (size_t)row * 128 + px0;
#pragma unroll
    for (int j2 = 0; j2 < 8; j2++) {
        const int o = wo * 64 + j2 * 8 + 2 * tig;
        if (o < 100) {
            const float* dd = &d[j2 * 4];
            const float b0 = offb[o], b1 = offb[o + 1];
            float* y0 = offout + ((size_t)(b * 100 + o)) * NPIX + outbase;
            float* y1 = y0 + NPIX;
            y0[pxl]     = dd[0] * 0.0009765625f + b0;
            y1[pxl]     = dd[1] * 0.0009765625f + b1;
            y0[pxl + 8] = dd[2] * 0.0009765625f + b0;
            y1[pxl + 8] = dd[3] * 0.0009765625f + b1;
        }
    }
}

// ---------------- deformable conv via mma.sync (fp16, single product) ------
// smem floats: sPy[3200] sPx[3200] sBNa[256] sBNb[256] | u32 Sbuf[2][4352]
// 3 CTAs/SM (187KB smem, 85-reg cap)
#define DEF_SMEM_BYTES (6912 * 4 + 2 * 4352 * 4)   // 62,464 B
__global__ void __launch_bounds__(256, 3) deform_hmma(
    const __half* __restrict__ xh,   // NHWC fp16 [b][p][256]
    const float* __restrict__ off,
    const uint2* __restrict__ BH,
    const float* __restrict__ bng, const float* __restrict__ bnb,
    const float* __restrict__ bnm, const float* __restrict__ bnv,
    float* __restrict__ yout) {
    float* sPy = smext;
    float* sPx = smext + 3200;
    float* sBNa = smext + 6400;
    float* sBNb = smext + 6656;
    uint32_t* Sbuf = (uint32_t*)(smext + 6912);

    const int tid = threadIdx.x;
    const int lane = tid & 31, warp = tid >> 5;
    const int b = blockIdx.y;
    const int row = blockIdx.x >> 1;
    const int px0 = (blockIdx.x & 1) << 6;

    const int wo = warp & 3;
    const int wp = warp >> 2;
    const int sh = warp & 1;
    const int cq = warp >> 1;
    const int lg = lane >> 3;
    const int c0s = cq * 32 + (lane & 7) * 4;

    if (tid < 256) {
        float inv = bng[tid] * rsqrtf(bnv[tid] + 1e-5f);
        sBNa[tid] = inv * 0.015625f;
        sBNb[tid] = bnb[tid] - bnm[tid] * inv;
    }
    for (int idx = tid; idx < 3200; idx += 256) {
        int gk = idx >> 6, p = idx & 63;
        int g = gk / 25, k = gk % 25;
        int kh = k / 5, kw = k % 5;
        int ch = b * 100 + g * 50 + 2 * k;
        float oy = off[(size_t)ch * NPIX + row * 128 + px0 + p];
        float ox = off[(size_t)(ch + 1) * NPIX + row * 128 + px0 + p];
        sPy[idx] = (float)(row + kh - 2) + oy;
        sPx[idx] = (float)(px0 + p + kw - 2) + ox;
    }
    __syncthreads();

    float d[64];
#pragma unroll
    for (int q = 0; q < 64; q++) d[q] = 0.f;

    const uint32_t sbase = smem_u32(Sbuf);
    const uint32_t lanePat = (lane & 15) * 272 + (lane >> 4) * 16;

    auto sample_tap = [&](int gk2, uint32_t* ShB) {
        const int gs = (gk2 >= 25) ? 1 : 0;
        const __half* xgb = xh + (size_t)b * NPIX * 256 + gs * 128 + c0s;
#pragma unroll
        for (int j = 0; j < 8; j++) {
            const int p = sh * 32 + j * 4 + lg;
            const float py = sPy[gk2 * 64 + p];
            const float pv = sPx[gk2 * 64 + p];
            const float y0f = floorf(py), x0f = floorf(pv);
            const float wy1 = py - y0f, wx1 = pv - x0f;
            const float wy0 = 1.f - wy1, wx0 = 1.f - wx1;
            const float w00 = wy0 * wx0, w01 = wy0 * wx1;
            const float w10 = wy1 * wx0, w11 = wy1 * wx1;
            const int iy = (int)y0f, ix = (int)x0f;
            const bool vy0 = (iy >= 0) & (iy < 128);
            const bool vy1 = (iy >= -1) & (iy < 127);
            const bool vx0 = (ix >= 0) & (ix < 128);
            const bool vx1 = (ix >= -1) & (ix < 127);
            const long base = ((long)iy * 128 + ix) * 256;
            const uint2 z2 = make_uint2(0u, 0u);
            uint2 ua = (vy0 & vx0) ? *(const uint2*)(xgb + base) : z2;
            uint2 ub = (vy0 & vx1) ? *(const uint2*)(xgb + base + 256) : z2;
            uint2 uc = (vy1 & vx0) ? *(const uint2*)(xgb + base + 128 * 256) : z2;
            uint2 ud = (vy1 & vx1) ? *(const uint2*)(xgb + base + 128 * 256 + 256) : z2;
            float2 a01 = __half22float2(*(__half2*)&ua.x);
            float2 a23 = __half22float2(*(__half2*)&ua.y);
            float2 b01 = __half22float2(*(__half2*)&ub.x);
            float2 b23 = __half22float2(*(__half2*)&ub.y);
            float2 c01 = __half22float2(*(__half2*)&uc.x);
            float2 c23 = __half22float2(*(__half2*)&uc.y);
            float2 e01 = __half22float2(*(__half2*)&ud.x);
            float2 e23 = __half22float2(*(__half2*)&ud.y);
            float r0 = w00 * a01.x + w01 * b01.x + w10 * c01.x + w11 * e01.x;
            float r1 = w00 * a01.y + w01 * b01.y + w10 * c01.y + w11 * e01.y;
            float r2 = w00 * a23.x + w01 * b23.x + w10 * c23.x + w11 * e23.x;
            float r3 = w00 * a23.y + w01 * b23.y + w10 * c23.y + w11 * e23.y;
            *(uint2*)&ShB[p * 68 + (c0s >> 1)] =
                make_uint2(packh(r0, r1), packh(r2, r3));
        }
    };

    sample_tap(0, Sbuf);
    __syncthreads();

    for (int gk = 0; gk < 50; gk++) {
        const int cur = gk & 1;
        if (gk < 49) sample_tap(gk + 1, Sbuf + (cur ^ 1) * 4352);
        const uint32_t aH = sbase + cur * 17408 + lanePat;
        const uint2* BHt = BH + ((size_t)gk * 8 * 32 + wo * 8) * 32 + lane;
#pragma unroll
        for (int s = 0; s < 8; s++) {
            uint32_t Ah[2][4];
            ldm4(Ah[0], aH + (wp * 32     ) * 272 + s * 32);
            ldm4(Ah[1], aH + (wp * 32 + 16) * 272 + s * 32);
            const uint2* bh = BHt + (size_t)s * 1024;
#pragma unroll
            for (int j2 = 0; j2 < 8; j2++) {
                uint2 Bh = bh[j2 * 32];
                float* d0 = &d[(0 * 8 + j2) * 4];
                float* d1 = &d[(1 * 8 + j2) * 4];
                mma16816(d0[0], d0[1], d0[2], d0[3], Ah[0], Bh.x, Bh.y);
                mma16816(d1[0], d1[1], d1[2], d1[3], Ah[1], Bh.x, Bh.y);
            }
        }
        __syncthreads();
    }

    const int ge = lane >> 2, tig = lane & 3;
    const size_t outbase = (size_t)row * 128 + px0;
#pragma unroll
    for (int mt = 0; mt < 2; mt++) {
#pragma unroll
        for (int j2 = 0; j2 < 8; j2++) {
            const float* dd = &d[(mt * 8 + j2) * 4];
            const int pxl = wp * 32 + mt * 16 + ge;
            const int o = wo * 64 + j2 * 8 + 2 * tig;
            float a0 = sBNa[o], b0v = sBNb[o];
            float a1 = sBNa[o + 1], b1v = sBNb[o + 1];
            float* y0 = yout + ((size_t)(b * 256 + o)) * NPIX + outbase;
            float* y1 = yout + ((size_t)(b * 256 + o + 1)) * NPIX + outbase;
            y0[pxl]     = fmaxf(dd[0] * a0 + b0v, 0.f);
            y1[pxl]     = fmaxf(dd[1] * a1 + b1v, 0.f);
            y0[pxl + 8] = fmaxf(dd[2] * a0 + b0v, 0.f);
            y1[pxl + 8] = fmaxf(dd[3] * a1 + b1v, 0.f);
        }
    }
}

// ---------------- SE / pool ----------------
__global__ void pool_kernel(const float* __restrict__ y, float* __restrict__ pool) {
    int bc = blockIdx.x;
    const float* plane = y + (size_t)bc * NPIX;
    float s = 0.f;
    for (int i = threadIdx.x; i < NPIX; i += 256) s += plane[i];
    __shared__ float red[256];
    red[threadIdx.x] = s;
    __syncthreads();
    for (int st = 128; st > 0; st >>= 1) {
        if (threadIdx.x < st) red[threadIdx.x] += red[threadIdx.x + st];
        __syncthreads();
    }
    if (threadIdx.x == 0) pool[bc] = red[0] * (1.f / NPIX);
}

__global__ void se_kernel(const float* __restrict__ pool,
                          const float* __restrict__ w1,
                          const float* __restrict__ w2,
                          float* __restrict__ scale) {
    int b = blockIdx.x;
    int tid = threadIdx.x;
    __shared__ float sp[256], shd[16];
    sp[tid] = pool[b * 256 + tid];
    __syncthreads();
    if (tid < 16) {
        float a = 0.f;
        for (int c = 0; c < 256; c++) a += sp[c] * w1[tid * 256 + c];
        shd[tid] = fmaxf(a, 0.f);
    }
    __syncthreads();
    float a = 0.f;
#pragma unroll
    for (int j = 0; j < 16; j++) a += shd[j] * w2[tid * 16 + j];
    scale[b * 256 + tid] = 1.f / (1.f + expf(-a));
}

// ---------------- final 1x1 conv + fused SE scale + BN + ReLU (fma2) ------
__global__ void __launch_bounds__(256) final_kernel(
    const float* __restrict__ xin, const float* __restrict__ sc,
    const float* __restrict__ redT,
    const float* __restrict__ bng, const float* __restrict__ bnb,
    const float* __restrict__ bnm, const float* __restrict__ bnv,
    float* __restrict__ out) {
    const int tid = threadIdx.x;
    const int b = blockIdx.y;
    const int p0 = blockIdx.x * 64;
    const int px = tid & 63, og = tid >> 6;
    __shared__ __align__(16) float sX[8][64];
    __shared__ __align__(16) float sWf[8][128];
    __shared__ float sBN[256];
    __shared__ float sSc[256];
    if (tid < 128) {
        float inv = bng[tid] * rsqrtf(bnv[tid] + 1e-5f);
        sBN[tid] = inv;
        sBN[128 + tid] = bnb[tid] - bnm[tid] * inv;
    }
    sSc[tid] = sc[b * 256 + tid];
    union { unsigned long long u[16]; float f[32]; } acc;
#pragma unroll
    for (int j = 0; j < 16; j++) acc.u[j] = 0ull;

    for (int cb = 0; cb < 256; cb += 8) {
        __syncthreads();
        {
            int i = tid;
            sX[i >> 6][i & 63] = xin[((size_t)(b * 256 + cb + (i >> 6))) * NPIX + p0 + (i & 63)]
                                 * sSc[cb + (i >> 6)];
            i = tid + 256;
            sX[i >> 6][i & 63] = xin[((size_t)(b * 256 + cb + (i >> 6))) * NPIX + p0 + (i & 63)]
                                 * sSc[cb + (i >> 6)];
            for (int t = tid; t < 1024; t += 256)
                sWf[t >> 7][t & 127] = redT[(cb + (t >> 7)) * 128 + (t & 127)];
        }
        __syncthreads();
#pragma unroll
        for (int c = 0; c < 8; c++) {
            float xv = sX[c][px];
            unsigned long long xd = pk2(xv, xv);
            const F4* wp = (const F4*)&sWf[c][og * 32];
#pragma unroll
            for (int j = 0; j < 8; j++) {
                F4 w = wp[j];
                fma2(acc.u[2 * j],     xd, w.u[0]);
                fma2(acc.u[2 * j + 1], xd, w.u[1]);
            }
        }
    }
#pragma unroll
    for (int j = 0; j < 32; j++) {
        int o = og * 32 + j;
        float v = acc.f[j] * sBN[o] + sBN[128 + o];
        out[((size_t)(b * 128 + o)) * NPIX + p0 + px] = fmaxf(v, 0.f);
    }
}

// ---------------- launch ----------------
extern "C" void kernel_launch(void* const* d_in, const int* in_sizes, int n_in,
                              void* d_out, int out_size) {
    const float* bev1   = (const float*)d_in[0];
    const float* bev2   = (const float*)d_in[1];
    const float* off_w1 = (const float*)d_in[2];
    const float* off_b1 = (const float*)d_in[3];
    const float* dcn_w1 = (const float*)d_in[4];
    const float* bn1_g  = (const float*)d_in[5];
    const float* bn1_b  = (const float*)d_in[6];
    const float* bn1_m  = (const float*)d_in[7];
    const float* bn1_v  = (const float*)d_in[8];
    const float* se1_w1 = (const float*)d_in[9];
    const float* se1_w2 = (const float*)d_in[10];
    const float* off_w2 = (const float*)d_in[11];
    const float* off_b2 = (const float*)d_in[12];
    const float* dcn_w2 = (const float*)d_in[13];
    const float* bn2_g  = (const float*)d_in[14];
    const float* bn2_b  = (const float*)d_in[15];
    const float* bn2_m  = (const float*)d_in[16];
    const float* bn2_v  = (const float*)d_in[17];
    const float* se2_w1 = (const float*)d_in[18];
    const float* se2_w2 = (const float*)d_in[19];
    const float* red_w  = (const float*)d_in[20];
    const float* bn3_g  = (const float*)d_in[21];
    const float* bn3_b  = (const float*)d_in[22];
    const float* bn3_m  = (const float*)d_in[23];
    const float* bn3_v  = (const float*)d_in[24];

    float *A, *B, *OFF, *RT, *POOL, *SCALE;
    __half *C;
    uint2 *BH, *OBH;
    cudaGetSymbolAddress((void**)&A,    g_bufA);
    cudaGetSymbolAddress((void**)&B,    g_bufB);
    cudaGetSymbolAddress((void**)&C,    g_bufC);
    cudaGetSymbolAddress((void**)&OFF,  g_off);
    cudaGetSymbolAddress((void**)&BH,   g_bh);
    cudaGetSymbolAddress((void**)&OBH,  g_obh);
    cudaGetSymbolAddress((void**)&RT,   g_rT);
    cudaGetSymbolAddress((void**)&POOL, g_pool);
    cudaGetSymbolAddress((void**)&SCALE,g_scale);

    const int OFF_SMEM = 2 * 4352 * 4;          // 34,816 B
    cudaFuncSetAttribute(offconv_hmma,
                         cudaFuncAttributeMaxDynamicSharedMemorySize, OFF_SMEM);
    cudaFuncSetAttribute(deform_hmma,
                         cudaFuncAttributeMaxDynamicSharedMemorySize, DEF_SMEM_BYTES);

    // ---- stage 1 ----
    concat_nhwc<<<dim3(512, 8, 4), 256>>>(bev1, bev2, C);
    prep_weights<<<2400, 256>>>(dcn_w1, off_w1, BH, OBH);
    offconv_hmma<<<dim3(256, 4), 256, OFF_SMEM>>>(C, OBH, off_b1, OFF);
    deform_hmma<<<dim3(256, 4), 256, DEF_SMEM_BYTES>>>(C, OFF, BH,
                                                 bn1_g, bn1_b, bn1_m, bn1_v, B);
    pool_kernel<<<1024, 256>>>(B, POOL);
    se_kernel<<<4, 256>>>(POOL, se1_w1, se1_w2, SCALE);

    // ---- stage 2 (scale1 fused into to_nhwc) ----
    to_nhwc_scaled<<<dim3(512, 8, 4), 256>>>(B, SCALE, C);
    prep_weights<<<2400, 256>>>(dcn_w2, off_w2, BH, OBH);
    offconv_hmma<<<dim3(256, 4), 256, OFF_SMEM>>>(C, OBH, off_b2, OFF);
    deform_hmma<<<dim3(256, 4), 256, DEF_SMEM_BYTES>>>(C, OFF, BH,
                                                 bn2_g, bn2_b, bn2_m, bn2_v, A);
    pool_kernel<<<1024, 256>>>(A, POOL);
    se_kernel<<<4, 256>>>(POOL, se2_w1, se2_w2, SCALE);

    // ---- final (scale2 fused) ----
    transpose_redw<<<128, 256>>>(red_w, RT);
    final_kernel<<<dim3(256, 4), 256>>>(A, SCALE, RT, bn3_g, bn3_b, bn3_m, bn3_v,
                                        (float*)d_out);
}

// round 17
// speedup vs baseline: 1.5272x; 1.5272x over previous
#include <cuda_runtime.h>
#include <cuda_fp16.h>
#include <math.h>
#include <stdint.h>

// ---------------- packed f32x2 helpers (final conv) ----------------
__device__ __forceinline__ unsigned long long pk2(float x, float y) {
    unsigned long long r;
    asm("mov.b64 %0, {%1, %2};" : "=l"(r) : "f"(x), "f"(y));
    return r;
}
__device__ __forceinline__ void fma2(unsigned long long& d,
                                     unsigned long long a, unsigned long long b) {
    asm("fma.rn.f32x2 %0, %1, %2, %0;" : "+l"(d) : "l"(a), "l"(b));
}
union F4 { float4 v; float f[4]; unsigned long long u[2]; };

// ---------------- mma.sync helpers ----------------
__device__ __forceinline__ void ldm4(uint32_t* r, uint32_t addr) {
    asm volatile("ldmatrix.sync.aligned.m8n8.x4.shared.b16 {%0,%1,%2,%3}, [%4];"
                 : "=r"(r[0]), "=r"(r[1]), "=r"(r[2]), "=r"(r[3]) : "r"(addr));
}
__device__ __forceinline__ void mma16816(float& d0, float& d1, float& d2, float& d3,
                                         const uint32_t* a, uint32_t b0, uint32_t b1) {
    asm volatile(
        "mma.sync.aligned.m16n8k16.row.col.f32.f16.f16.f32 "
        "{%0,%1,%2,%3}, {%4,%5,%6,%7}, {%8,%9}, {%0,%1,%2,%3};"
        : "+f"(d0), "+f"(d1), "+f"(d2), "+f"(d3)
        : "r"(a[0]), "r"(a[1]), "r"(a[2]), "r"(a[3]), "r"(b0), "r"(b1));
}
__device__ __forceinline__ uint32_t smem_u32(const void* p) {
    uint32_t a;
    asm("{ .reg .u64 t; cvta.to.shared.u64 t, %1; cvt.u32.u64 %0, t; }"
        : "=r"(a) : "l"(p));
    return a;
}
__device__ __forceinline__ uint32_t packh(float a, float b) {
    __half2 h = __halves2half2(__float2half_rn(a), __float2half_rn(b));
    return *(uint32_t*)&h;
}

// single extern smem symbol shared by kernels
extern __shared__ float smext[];

// ---------------- scratch ----------------
#define NPIX 16384
__device__ __align__(16) float  g_bufA[4 * 256 * NPIX];
__device__ __align__(16) float  g_bufB[4 * 256 * NPIX];
__device__ __align__(16) __half g_bufC[4 * 256 * NPIX];   // NHWC fp16
__device__ __align__(16) float  g_off [4 * 100 * NPIX];
__device__ __align__(16) uint2  g_bh  [50 * 8 * 32 * 32];
__device__ __align__(16) uint2  g_obh [50 * 8 * 16 * 32];
__device__ __align__(16) float  g_rT  [256 * 128];
__device__ float g_pool[1024];
__device__ float g_scale[1024];

// ---------------- concat -> NHWC fp16 C ----------
__global__ void __launch_bounds__(256) concat_nhwc(
    const float* __restrict__ bev1, const float* __restrict__ bev2,
    __half* __restrict__ C) {
    __shared__ float tile[32][33];
    const int bp = blockIdx.x, bc = blockIdx.y, b = blockIdx.z;
    const int tx = threadIdx.x & 31, ty = threadIdx.x >> 5;
    const float* src = ((bc < 4)
        ? bev1 + ((size_t)b * 128 + bc * 32) * NPIX
        : bev2 + ((size_t)b * 128 + (bc - 4) * 32) * NPIX) + bp * 32;
#pragma unroll
    for (int r = 0; r < 4; r++) {
        int c = ty + r * 8;
        tile[c][tx] = src[(size_t)c * NPIX + tx];
    }
    __syncthreads();
    __half* dst = C + ((size_t)b * NPIX + bp * 32) * 256 + bc * 32;
#pragma unroll
    for (int r = 0; r < 4; r++) {
        int p = ty + r * 8;
        dst[(size_t)p * 256 + tx] = __float2half_rn(tile[tx][p]);
    }
}

// ---------------- NCHW -> NHWC fp16 transpose with fused SE scale ----------
__global__ void __launch_bounds__(256) to_nhwc_scaled(
    const float* __restrict__ in, const float* __restrict__ sc,
    __half* __restrict__ outp) {
    __shared__ float tile[32][33];
    __shared__ float sSc[32];
    const int bp = blockIdx.x, bc = blockIdx.y, b = blockIdx.z;
    const int tx = threadIdx.x & 31, ty = threadIdx.x >> 5;
    if (threadIdx.x < 32) sSc[threadIdx.x] = sc[b * 256 + bc * 32 + threadIdx.x];
    const float* src = in + ((size_t)b * 256 + bc * 32) * NPIX + bp * 32;
#pragma unroll
    for (int r = 0; r < 4; r++) {
        int c = ty + r * 8;
        tile[c][tx] = src[(size_t)c * NPIX + tx];
    }
    __syncthreads();
    __half* dst = outp + ((size_t)b * NPIX + bp * 32) * 256 + bc * 32;
    const float s = sSc[tx];
#pragma unroll
    for (int r = 0; r < 4; r++) {
        int p = ty + r * 8;
        dst[(size_t)p * 256 + tx] = __float2half_rn(tile[tx][p] * s);
    }
}

// ---------------- weight prep: dcn hi + off hi fragment packs --------------
__global__ void prep_weights(const float* __restrict__ dcnw,
                             const float* __restrict__ offw,
                             uint2* __restrict__ BH,
                             uint2* __restrict__ OBH) {
    int idx = blockIdx.x * 256 + threadIdx.x;
    if (idx < 409600) {
        const int t  = idx & 31;
        const int j  = (idx >> 5) & 31;
        const int s  = (idx >> 10) & 7;
        const int gk = idx >> 13;
        const int k = gk % 25, g = gk / 25;
        const int o = j * 8 + (t >> 2);
        const int c0 = s * 16 + 2 * (t & 3);
        float w0 = dcnw[o * 6400 + (g * 128 + c0    ) * 25 + k] * 64.f;
        float w1 = dcnw[o * 6400 + (g * 128 + c0 + 1) * 25 + k] * 64.f;
        float w8 = dcnw[o * 6400 + (g * 128 + c0 + 8) * 25 + k] * 64.f;
        float w9 = dcnw[o * 6400 + (g * 128 + c0 + 9) * 25 + k] * 64.f;
        BH[idx] = make_uint2(packh(__half2float(__float2half_rn(w0)),
                                   __half2float(__float2half_rn(w1))),
                             packh(__half2float(__float2half_rn(w8)),
                                   __half2float(__float2half_rn(w9))));
    } else if (idx < 614400) {
        const int i2 = idx - 409600;
        const int t  = i2 & 31;
        const int j  = (i2 >> 5) & 15;
        const int s  = (i2 >> 9) & 7;
        const int it = i2 >> 12;
        const int k = it >> 1, h = it & 1;
        const int o = j * 8 + (t >> 2);
        const int c0 = h * 128 + s * 16 + 2 * (t & 3);
        float w0 = 0.f, w1 = 0.f, w8 = 0.f, w9 = 0.f;
        if (o < 100) {
            w0 = offw[o * 6400 + (c0    ) * 25 + k] * 1024.f;
            w1 = offw[o * 6400 + (c0 + 1) * 25 + k] * 1024.f;
            w8 = offw[o * 6400 + (c0 + 8) * 25 + k] * 1024.f;
            w9 = offw[o * 6400 + (c0 + 9) * 25 + k] * 1024.f;
        }
        OBH[i2] = make_uint2(packh(__half2float(__float2half_rn(w0)),
                                   __half2float(__float2half_rn(w1))),
                             packh(__half2float(__float2half_rn(w8)),
                                   __half2float(__float2half_rn(w9))));
    }
}

__global__ void transpose_redw(const float* __restrict__ w, float* __restrict__ dst) {
    int idx = blockIdx.x * 256 + threadIdx.x;
    int o = idx & 127;
    int c = idx >> 7;
    dst[idx] = w[o * 256 + c];
}

// ---------------- offset conv via mma.sync (fp16 in, single product) -------
// dynamic smem: uint32 Sbuf[2][4352] = 34,816 B; 2 CTAs/SM
__global__ void __launch_bounds__(256, 2) offconv_hmma(
    const __half* __restrict__ xh,   // NHWC fp16 [b][p][256]
    const uint2* __restrict__ OBH,
    const float* __restrict__ offb,
    float* __restrict__ offout) {
    uint32_t* Sbuf = (uint32_t*)smext;

    const int tid = threadIdx.x;
    const int lane = tid & 31, warp = tid >> 5;
    const int b = blockIdx.y;
    const int row = blockIdx.x >> 1;
    const int px0 = (blockIdx.x & 1) << 6;

    const int wo = warp & 1;
    const int wp = warp >> 1;
    const int sh = warp & 1;
    const int cq = warp >> 1;
    const int lg = lane >> 3;
    const int c0s = cq * 32 + (lane & 7) * 4;

    float d[32];
#pragma unroll
    for (int q = 0; q < 32; q++) d[q] = 0.f;

    const uint32_t sbase = smem_u32(Sbuf);
    const uint32_t lanePat = (lane & 15) * 272 + (lane >> 4) * 16;
    const __half* xb = xh + (size_t)b * NPIX * 256;

    auto sample_tap = [&](int it2, uint32_t* ShB) {
        const int k2 = it2 >> 1, h2 = it2 & 1;
        const int kh2 = k2 / 5, kw2 = k2 % 5;
        const int gy2 = row + kh2 - 2;
        const bool vy2 = (gy2 >= 0) & (gy2 < 128);
#pragma unroll
        for (int j = 0; j < 8; j++) {
            const int p = sh * 32 + j * 4 + lg;
            const int gx = px0 + p + kw2 - 2;
            uint2 va = make_uint2(0u, 0u);
            if (vy2 && gx >= 0 && gx < 128)
                va = *(const uint2*)(xb + ((size_t)gy2 * 128 + gx) * 256 + h2 * 128 + c0s);
            *(uint2*)&ShB[p * 68 + (c0s >> 1)] = va;
        }
    };

    sample_tap(0, Sbuf);
    __syncthreads();

    for (int it = 0; it < 50; it++) {
        const int cur = it & 1;
        if (it < 49) sample_tap(it + 1, Sbuf + (cur ^ 1) * 4352);
        const uint32_t aH = sbase + cur * 17408 + lanePat;
        const uint2* BHt = OBH + ((size_t)it * 8 * 16 + wo * 8) * 32 + lane;
#pragma unroll
        for (int s = 0; s < 8; s++) {
            uint32_t Ah[4];
            ldm4(Ah, aH + (wp * 16) * 272 + s * 32);
            const uint2* bh = BHt + (size_t)s * 512;
#pragma unroll
            for (int j2 = 0; j2 < 8; j2++) {
                uint2 Bh = bh[j2 * 32];
                float* dd = &d[j2 * 4];
                mma16816(dd[0], dd[1], dd[2], dd[3], Ah, Bh.x, Bh.y);
            }
        }
        __syncthreads();
    }

    const int g2 = lane >> 2, tig = lane & 3;
    const int pxl = wp * 16 + g2;
    const size_t outbase = (size_t)row * 128 + px0;
#pragma unroll
    for (int j2 = 0; j2 < 8; j2++) {
        const int o = wo * 64 + j2 * 8 + 2 * tig;
        if (o < 100) {
            const float* dd = &d[j2 * 4];
            const float b0 = offb[o], b1 = offb[o + 1];
            float* y0 = offout + ((size_t)(b * 100 + o)) * NPIX + outbase;
            float* y1 = y0 + NPIX;
            y0[pxl]     = dd[0] * 0.0009765625f + b0;
            y1[pxl]     = dd[1] * 0.0009765625f + b1;
            y0[pxl + 8] = dd[2] * 0.0009765625f + b0;
            y1[pxl + 8] = dd[3] * 0.0009765625f + b1;
        }
    }
}

// ---------------- deformable conv via mma.sync (fp16, single product) ------
// smem floats: sPy[3200] sPx[3200] sBNa[256] sBNb[256] | u32 Sbuf[2][4352]
// 2 CTAs/SM (verified sweet spot)
#define DEF_SMEM_BYTES (6912 * 4 + 2 * 4352 * 4)   // 62,464 B
__global__ void __launch_bounds__(256, 2) deform_hmma(
    const __half* __restrict__ xh,   // NHWC fp16 [b][p][256]
    const float* __restrict__ off,
    const uint2* __restrict__ BH,
    const float* __restrict__ bng, const float* __restrict__ bnb,
    const float* __restrict__ bnm, const float* __restrict__ bnv,
    float* __restrict__ yout) {
    float* sPy = smext;
    float* sPx = smext + 3200;
    float* sBNa = smext + 6400;
    float* sBNb = smext + 6656;
    uint32_t* Sbuf = (uint32_t*)(smext + 6912);

    const int tid = threadIdx.x;
    const int lane = tid & 31, warp = tid >> 5;
    const int b = blockIdx.y;
    const int row = blockIdx.x >> 1;
    const int px0 = (blockIdx.x & 1) << 6;

    const int wo = warp & 3;
    const int wp = warp >> 2;
    const int sh = warp & 1;
    const int cq = warp >> 1;
    const int lg = lane >> 3;
    const int c0s = cq * 32 + (lane & 7) * 4;

    if (tid < 256) {
        float inv = bng[tid] * rsqrtf(bnv[tid] + 1e-5f);
        sBNa[tid] = inv * 0.015625f;
        sBNb[tid] = bnb[tid] - bnm[tid] * inv;
    }
    for (int idx = tid; idx < 3200; idx += 256) {
        int gk = idx >> 6, p = idx & 63;
        int g = gk / 25, k = gk % 25;
        int kh = k / 5, kw = k % 5;
        int ch = b * 100 + g * 50 + 2 * k;
        float oy = off[(size_t)ch * NPIX + row * 128 + px0 + p];
        float ox = off[(size_t)(ch + 1) * NPIX + row * 128 + px0 + p];
        sPy[idx] = (float)(row + kh - 2) + oy;
        sPx[idx] = (float)(px0 + p + kw - 2) + ox;
    }
    __syncthreads();

    float d[64];
#pragma unroll
    for (int q = 0; q < 64; q++) d[q] = 0.f;

    const uint32_t sbase = smem_u32(Sbuf);
    const uint32_t lanePat = (lane & 15) * 272 + (lane >> 4) * 16;

    auto sample_tap = [&](int gk2, uint32_t* ShB) {
        const int gs = (gk2 >= 25) ? 1 : 0;
        const __half* xgb = xh + (size_t)b * NPIX * 256 + gs * 128 + c0s;
#pragma unroll
        for (int j = 0; j < 8; j++) {
            const int p = sh * 32 + j * 4 + lg;
            const float py = sPy[gk2 * 64 + p];
            const float pv = sPx[gk2 * 64 + p];
            const float y0f = floorf(py), x0f = floorf(pv);
            const float wy1 = py - y0f, wx1 = pv - x0f;
            const float wy0 = 1.f - wy1, wx0 = 1.f - wx1;
            const float w00 = wy0 * wx0, w01 = wy0 * wx1;
            const float w10 = wy1 * wx0, w11 = wy1 * wx1;
            const int iy = (int)y0f, ix = (int)x0f;
            const bool vy0 = (iy >= 0) & (iy < 128);
            const bool vy1 = (iy >= -1) & (iy < 127);
            const bool vx0 = (ix >= 0) & (ix < 128);
            const bool vx1 = (ix >= -1) & (ix < 127);
            const long base = ((long)iy * 128 + ix) * 256;
            const uint2 z2 = make_uint2(0u, 0u);
            uint2 ua = (vy0 & vx0) ? *(const uint2*)(xgb + base) : z2;
            uint2 ub = (vy0 & vx1) ? *(const uint2*)(xgb + base + 256) : z2;
            uint2 uc = (vy1 & vx0) ? *(const uint2*)(xgb + base + 128 * 256) : z2;
            uint2 ud = (vy1 & vx1) ? *(const uint2*)(xgb + base + 128 * 256 + 256) : z2;
            float2 a01 = __half22float2(*(__half2*)&ua.x);
            float2 a23 = __half22float2(*(__half2*)&ua.y);
            float2 b01 = __half22float2(*(__half2*)&ub.x);
            float2 b23 = __half22float2(*(__half2*)&ub.y);
            float2 c01 = __half22float2(*(__half2*)&uc.x);
            float2 c23 = __half22float2(*(__half2*)&uc.y);
            float2 e01 = __half22float2(*(__half2*)&ud.x);
            float2 e23 = __half22float2(*(__half2*)&ud.y);
            float r0 = w00 * a01.x + w01 * b01.x + w10 * c01.x + w11 * e01.x;
            float r1 = w00 * a01.y + w01 * b01.y + w10 * c01.y + w11 * e01.y;
            float r2 = w00 * a23.x + w01 * b23.x + w10 * c23.x + w11 * e23.x;
            float r3 = w00 * a23.y + w01 * b23.y + w10 * c23.y + w11 * e23.y;
            *(uint2*)&ShB[p * 68 + (c0s >> 1)] =
                make_uint2(packh(r0, r1), packh(r2, r3));
        }
    };

    sample_tap(0, Sbuf);
    __syncthreads();

    for (int gk = 0; gk < 50; gk++) {
        const int cur = gk & 1;
        if (gk < 49) sample_tap(gk + 1, Sbuf + (cur ^ 1) * 4352);
        const uint32_t aH = sbase + cur * 17408 + lanePat;
        const uint2* BHt = BH + ((size_t)gk * 8 * 32 + wo * 8) * 32 + lane;
#pragma unroll
        for (int s = 0; s < 8; s++) {
            uint32_t Ah[2][4];
            ldm4(Ah[0], aH + (wp * 32     ) * 272 + s * 32);
            ldm4(Ah[1], aH + (wp * 32 + 16) * 272 + s * 32);
            const uint2* bh = BHt + (size_t)s * 1024;
#pragma unroll
            for (int j2 = 0; j2 < 8; j2++) {
                uint2 Bh = bh[j2 * 32];
                float* d0 = &d[(0 * 8 + j2) * 4];
                float* d1 = &d[(1 * 8 + j2) * 4];
                mma16816(d0[0], d0[1], d0[2], d0[3], Ah[0], Bh.x, Bh.y);
                mma16816(d1[0], d1[1], d1[2], d1[3], Ah[1], Bh.x, Bh.y);
            }
        }
        __syncthreads();
    }

    const int ge = lane >> 2, tig = lane & 3;
    const size_t outbase = (size_t)row * 128 + px0;
#pragma unroll
    for (int mt = 0; mt < 2; mt++) {
#pragma unroll
        for (int j2 = 0; j2 < 8; j2++) {
            const float* dd = &d[(mt * 8 + j2) * 4];
            const int pxl = wp * 32 + mt * 16 + ge;
            const int o = wo * 64 + j2 * 8 + 2 * tig;
            float a0 = sBNa[o], b0v = sBNb[o];
            float a1 = sBNa[o + 1], b1v = sBNb[o + 1];
            float* y0 = yout + ((size_t)(b * 256 + o)) * NPIX + outbase;
            float* y1 = yout + ((size_t)(b * 256 + o + 1)) * NPIX + outbase;
            y0[pxl]     = fmaxf(dd[0] * a0 + b0v, 0.f);
            y1[pxl]     = fmaxf(dd[1] * a1 + b1v, 0.f);
            y0[pxl + 8] = fmaxf(dd[2] * a0 + b0v, 0.f);
            y1[pxl + 8] = fmaxf(dd[3] * a1 + b1v, 0.f);
        }
    }
}

// ---------------- SE / pool ----------------
__global__ void pool_kernel(const float* __restrict__ y, float* __restrict__ pool) {
    int bc = blockIdx.x;
    const float* plane = y + (size_t)bc * NPIX;
    float s = 0.f;
    for (int i = threadIdx.x; i < NPIX; i += 256) s += plane[i];
    __shared__ float red[256];
    red[threadIdx.x] = s;
    __syncthreads();
    for (int st = 128; st > 0; st >>= 1) {
        if (threadIdx.x < st) red[threadIdx.x] += red[threadIdx.x + st];
        __syncthreads();
    }
    if (threadIdx.x == 0) pool[bc] = red[0] * (1.f / NPIX);
}

__global__ void se_kernel(const float* __restrict__ pool,
                          const float* __restrict__ w1,
                          const float* __restrict__ w2,
                          float* __restrict__ scale) {
    int b = blockIdx.x;
    int tid = threadIdx.x;
    __shared__ float sp[256], shd[16];
    sp[tid] = pool[b * 256 + tid];
    __syncthreads();
    if (tid < 16) {
        float a = 0.f;
        for (int c = 0; c < 256; c++) a += sp[c] * w1[tid * 256 + c];
        shd[tid] = fmaxf(a, 0.f);
    }
    __syncthreads();
    float a = 0.f;
#pragma unroll
    for (int j = 0; j < 16; j++) a += shd[j] * w2[tid * 16 + j];
    scale[b * 256 + tid] = 1.f / (1.f + expf(-a));
}

// ---------------- final 1x1 conv + fused SE scale + BN + ReLU (fma2) ------
__global__ void __launch_bounds__(256) final_kernel(
    const float* __restrict__ xin, const float* __restrict__ sc,
    const float* __restrict__ redT,
    const float* __restrict__ bng, const float* __restrict__ bnb,
    const float* __restrict__ bnm, const float* __restrict__ bnv,
    float* __restrict__ out) {
    const int tid = threadIdx.x;
    const int b = blockIdx.y;
    const int p0 = blockIdx.x * 64;
    const int px = tid & 63, og = tid >> 6;
    __shared__ __align__(16) float sX[8][64];
    __shared__ __align__(16) float sWf[8][128];
    __shared__ float sBN[256];
    __shared__ float sSc[256];
    if (tid < 128) {
        float inv = bng[tid] * rsqrtf(bnv[tid] + 1e-5f);
        sBN[tid] = inv;
        sBN[128 + tid] = bnb[tid] - bnm[tid] * inv;
    }
    sSc[tid] = sc[b * 256 + tid];
    union { unsigned long long u[16]; float f[32]; } acc;
#pragma unroll
    for (int j = 0; j < 16; j++) acc.u[j] = 0ull;

    for (int cb = 0; cb < 256; cb += 8) {
        __syncthreads();
        {
            int i = tid;
            sX[i >> 6][i & 63] = xin[((size_t)(b * 256 + cb + (i >> 6))) * NPIX + p0 + (i & 63)]
                                 * sSc[cb + (i >> 6)];
            i = tid + 256;
            sX[i >> 6][i & 63] = xin[((size_t)(b * 256 + cb + (i >> 6))) * NPIX + p0 + (i & 63)]
                                 * sSc[cb + (i >> 6)];
            for (int t = tid; t < 1024; t += 256)
                sWf[t >> 7][t & 127] = redT[(cb + (t >> 7)) * 128 + (t & 127)];
        }
        __syncthreads();
#pragma unroll
        for (int c = 0; c < 8; c++) {
            float xv = sX[c][px];
            unsigned long long xd = pk2(xv, xv);
            const F4* wp = (const F4*)&sWf[c][og * 32];
#pragma unroll
            for (int j = 0; j < 8; j++) {
                F4 w = wp[j];
                fma2(acc.u[2 * j],     xd, w.u[0]);
                fma2(acc.u[2 * j + 1], xd, w.u[1]);
            }
        }
    }
#pragma unroll
    for (int j = 0; j < 32; j++) {
        int o = og * 32 + j;
        float v = acc.f[j] * sBN[o] + sBN[128 + o];
        out[((size_t)(b * 128 + o)) * NPIX + p0 + px] = fmaxf(v, 0.f);
    }
}

// ---------------- launch ----------------
extern "C" void kernel_launch(void* const* d_in, const int* in_sizes, int n_in,
                              void* d_out, int out_size) {
    const float* bev1   = (const float*)d_in[0];
    const float* bev2   = (const float*)d_in[1];
    const float* off_w1 = (const float*)d_in[2];
    const float* off_b1 = (const float*)d_in[3];
    const float* dcn_w1 = (const float*)d_in[4];
    const float* bn1_g  = (const float*)d_in[5];
    const float* bn1_b  = (const float*)d_in[6];
    const float* bn1_m  = (const float*)d_in[7];
    const float* bn1_v  = (const float*)d_in[8];
    const float* se1_w1 = (const float*)d_in[9];
    const float* se1_w2 = (const float*)d_in[10];
    const float* off_w2 = (const float*)d_in[11];
    const float* off_b2 = (const float*)d_in[12];
    const float* dcn_w2 = (const float*)d_in[13];
    const float* bn2_g  = (const float*)d_in[14];
    const float* bn2_b  = (const float*)d_in[15];
    const float* bn2_m  = (const float*)d_in[16];
    const float* bn2_v  = (const float*)d_in[17];
    const float* se2_w1 = (const float*)d_in[18];
    const float* se2_w2 = (const float*)d_in[19];
    const float* red_w  = (const float*)d_in[20];
    const float* bn3_g  = (const float*)d_in[21];
    const float* bn3_b  = (const float*)d_in[22];
    const float* bn3_m  = (const float*)d_in[23];
    const float* bn3_v  = (const float*)d_in[24];

    float *A, *B, *OFF, *RT, *POOL, *SCALE;
    __half *C;
    uint2 *BH, *OBH;
    cudaGetSymbolAddress((void**)&A,    g_bufA);
    cudaGetSymbolAddress((void**)&B,    g_bufB);
    cudaGetSymbolAddress((void**)&C,    g_bufC);
    cudaGetSymbolAddress((void**)&OFF,  g_off);
    cudaGetSymbolAddress((void**)&BH,   g_bh);
    cudaGetSymbolAddress((void**)&OBH,  g_obh);
    cudaGetSymbolAddress((void**)&RT,   g_rT);
    cudaGetSymbolAddress((void**)&POOL, g_pool);
    cudaGetSymbolAddress((void**)&SCALE,g_scale);

    const int OFF_SMEM = 2 * 4352 * 4;          // 34,816 B
    cudaFuncSetAttribute(offconv_hmma,
                         cudaFuncAttributeMaxDynamicSharedMemorySize, OFF_SMEM);
    cudaFuncSetAttribute(deform_hmma,
                         cudaFuncAttributeMaxDynamicSharedMemorySize, DEF_SMEM_BYTES);

    // ---- stage 1 ----
    concat_nhwc<<<dim3(512, 8, 4), 256>>>(bev1, bev2, C);
    prep_weights<<<2400, 256>>>(dcn_w1, off_w1, BH, OBH);
    offconv_hmma<<<dim3(256, 4), 256, OFF_SMEM>>>(C, OBH, off_b1, OFF);
    deform_hmma<<<dim3(256, 4), 256, DEF_SMEM_BYTES>>>(C, OFF, BH,
                                                 bn1_g, bn1_b, bn1_m, bn1_v, B);
    pool_kernel<<<1024, 256>>>(B, POOL);
    se_kernel<<<4, 256>>>(POOL, se1_w1, se1_w2, SCALE);

    // ---- stage 2 (scale1 fused into to_nhwc) ----
    to_nhwc_scaled<<<dim3(512, 8, 4), 256>>>(B, SCALE, C);
    prep_weights<<<2400, 256>>>(dcn_w2, off_w2, BH, OBH);
    offconv_hmma<<<dim3(256, 4), 256, OFF_SMEM>>>(C, OBH, off_b2, OFF);
    deform_hmma<<<dim3(256, 4), 256, DEF_SMEM_BYTES>>>(C, OFF, BH,
                                                 bn2_g, bn2_b, bn2_m, bn2_v, A);
    pool_kernel<<<1024, 256>>>(A, POOL);
    se_kernel<<<4, 256>>>(POOL, se2_w1, se2_w2, SCALE);

    // ---- final (scale2 fused) ----
    transpose_redw<<<128, 256>>>(red_w, RT);
    final_kernel<<<dim3(256, 4), 256>>>(A, SCALE, RT, bn3_g, bn3_b, bn3_m, bn3_v,
                                        (float*)d_out);
}